// round 5
// baseline (speedup 1.0000x reference)
#include <cuda_runtime.h>

// Problem constants
#define L_   12
#define B_   4
#define H_   12
#define S_   785          // seq incl. CLS
#define NP   784          // LayerNorm width
#define KS   588          // 1-based k-th smallest
#define LN_EPS 1e-5f

// Reduction tiling: one block per (l,h,b) slice, all 784 non-CLS rows.
#define NPART  144                  // partials per b = L*H
#define ROWS   784                  // rows summed per block
#define ACC    14                   // accumulators (MLP depth); 784 = 14*56
#define ITERS  (ROWS / ACC)         // 56

// Deterministic scratch (device globals — no allocation in kernel_launch)
__device__ float g_part1[B_ * NPART * S_];   // ~1.8 MB

// ---------------------------------------------------------------------------
// Kernel 1: streaming column sums.
// Block = (lh, b). Thread tid owns column tid (0..784); sums all 784 rows
// with 14 independent accumulators (deep LDG batch -> high MLP -> DRAM sat).
// Perfectly coalesced: a warp's LDG.32 covers 128 contiguous bytes.
// ---------------------------------------------------------------------------
__global__ __launch_bounds__(800, 2)
void colsum_kernel(const float* __restrict__ att) {
    const int tid = threadIdx.x;
    if (tid >= S_) return;
    const int lh = blockIdx.x;        // 0..143
    const int b  = blockIdx.y;        // 0..3

    const int l = lh / H_;
    const int h = lh - l * H_;

    const size_t base =
        ((((size_t)l * B_ + b) * H_ + h) * S_ + 1) * (size_t)S_ + tid;  // skip CLS row
    const float* __restrict__ p = att + base;

    float a0 = 0.f, a1 = 0.f, a2 = 0.f, a3 = 0.f, a4 = 0.f, a5 = 0.f, a6 = 0.f;
    float a7 = 0.f, a8 = 0.f, a9 = 0.f, a10 = 0.f, a11 = 0.f, a12 = 0.f, a13 = 0.f;

    #pragma unroll 1
    for (int r = 0; r < ITERS; ++r) {
        a0  += p[ 0 * S_];
        a1  += p[ 1 * S_];
        a2  += p[ 2 * S_];
        a3  += p[ 3 * S_];
        a4  += p[ 4 * S_];
        a5  += p[ 5 * S_];
        a6  += p[ 6 * S_];
        a7  += p[ 7 * S_];
        a8  += p[ 8 * S_];
        a9  += p[ 9 * S_];
        a10 += p[10 * S_];
        a11 += p[11 * S_];
        a12 += p[12 * S_];
        a13 += p[13 * S_];
        p += ACC * S_;
    }
    // fixed pairwise tree (deterministic)
    float s01 = a0 + a1,  s23 = a2 + a3,  s45 = a4 + a5,  s67 = a6 + a7;
    float s89 = a8 + a9,  sab = a10 + a11, scd = a12 + a13;
    float t0 = s01 + s23, t1 = s45 + s67, t2 = s89 + sab;
    float sum = (t0 + t1) + (t2 + scd);

    g_part1[((size_t)b * NPART + lh) * S_ + tid] = sum;
}

// ---------------------------------------------------------------------------
// Kernel 2: fused per-batch finalize. Reduce 144 partials per column (L2-hot,
// coalesced across threads), /144, LayerNorm, rank-based kthvalue threshold
// (sigmoid is monotone, so rank on ln directly), write mask.
// One block per b, 1024 threads (784 active columns).
// ---------------------------------------------------------------------------
__global__ __launch_bounds__(1024, 1)
void finalize_kernel(const float* __restrict__ gamma,
                     const float* __restrict__ beta,
                     float* __restrict__ out) {
    __shared__ float red[1024];
    __shared__ float sv[NP];
    __shared__ float s_mu, s_rstd, s_thr;

    const int b = blockIdx.x;
    const int t = threadIdx.x;

    float s = 0.f;
    if (t < NP) {
        // column t of output = column (t+1) of the 785-wide partials
        const float* __restrict__ src = g_part1 + (size_t)b * NPART * S_ + (t + 1);
        #pragma unroll 8
        for (int k = 0; k < NPART; ++k) s += src[(size_t)k * S_];
        s *= (1.0f / (L_ * H_));    // mean over heads then layers
    }

    // mean
    red[t] = (t < NP) ? s : 0.f;
    __syncthreads();
    for (int o = 512; o > 0; o >>= 1) {
        if (t < o) red[t] += red[t + o];
        __syncthreads();
    }
    if (t == 0) s_mu = red[0] / NP;
    __syncthreads();
    const float mu = s_mu;

    // variance
    const float d = (t < NP) ? (s - mu) : 0.f;
    red[t] = d * d;
    __syncthreads();
    for (int o = 512; o > 0; o >>= 1) {
        if (t < o) red[t] += red[t + o];
        __syncthreads();
    }
    if (t == 0) s_rstd = rsqrtf(red[0] / NP + LN_EPS);
    __syncthreads();

    if (t < NP) sv[t] = d * s_rstd * gamma[t] + beta[t];
    __syncthreads();

    // k-th smallest by rank counting (ties handled: rank interval covers k-1)
    if (t < NP) {
        const float v = sv[t];
        int cl = 0, ce = 0;
        #pragma unroll 4
        for (int j = 0; j < NP; ++j) {
            const float x = sv[j];
            cl += (x < v);
            ce += (x == v);
        }
        if (cl <= (KS - 1) && cl + ce > (KS - 1)) s_thr = v;
    }
    __syncthreads();

    if (t < NP) out[(size_t)b * NP + t] = (sv[t] > s_thr) ? 1.0f : 0.0f;
}

// ---------------------------------------------------------------------------
extern "C" void kernel_launch(void* const* d_in, const int* in_sizes, int n_in,
                              void* d_out, int out_size) {
    const float* att   = (const float*)d_in[0];
    const float* gamma = (const float*)d_in[1];
    const float* beta  = (const float*)d_in[2];
    float* out = (float*)d_out;

    colsum_kernel<<<dim3(NPART, B_), 800>>>(att);
    finalize_kernel<<<B_, 1024>>>(gamma, beta, out);
}

// round 7
// speedup vs baseline: 1.2936x; 1.2936x over previous
#include <cuda_runtime.h>

// Problem constants
#define L_   12
#define B_   4
#define H_   12
#define S_   785          // seq incl. CLS
#define NP   784          // LayerNorm width
#define KS   588          // 1-based k-th smallest
#define LN_EPS 1e-5f

// Stage-1 tiling (R4 known-good config)
#define CH     2                   // row chunks per (b, l, h)
#define ROWS_PER_CHUNK 392         // 784 / CH
#define NPART  (144 * CH)          // 288 partials per b

// Stage-2 tiling
#define KGRP   8                   // k-groups per reduce2 block
#define PER_KG (NPART / KGRP)      // 36

// Deterministic scratch (device globals — no allocation in kernel_launch)
__device__ float g_part1[B_ * NPART * S_];   // ~3.6 MB
__device__ float g_s[B_ * NP];               // final column sums / 144

// ---------------------------------------------------------------------------
// Kernel 1: streaming column sums (identical to the 221us R4 version).
// Block = (chunk, lh, b). Thread tid owns column tid (0..784); sums 392 rows
// with 8 independent accumulators. Warp LDG.32 covers 128 contiguous bytes.
// ---------------------------------------------------------------------------
__global__ __launch_bounds__(800, 2)
void colsum_kernel(const float* __restrict__ att) {
    const int tid   = threadIdx.x;
    if (tid >= S_) return;
    const int chunk = blockIdx.x;     // 0..CH-1
    const int lh    = blockIdx.y;     // 0..143
    const int b     = blockIdx.z;     // 0..3

    const int l = lh / H_;
    const int h = lh - l * H_;
    const int i0 = 1 + chunk * ROWS_PER_CHUNK;   // skip CLS row (i = 0)

    const size_t base =
        ((((size_t)l * B_ + b) * H_ + h) * S_ + i0) * (size_t)S_ + tid;
    const float* __restrict__ p = att + base;

    float a0 = 0.f, a1 = 0.f, a2 = 0.f, a3 = 0.f;
    float a4 = 0.f, a5 = 0.f, a6 = 0.f, a7 = 0.f;

    #pragma unroll 1
    for (int r = 0; r < ROWS_PER_CHUNK / 8; ++r) {
        a0 += p[0 * S_];
        a1 += p[1 * S_];
        a2 += p[2 * S_];
        a3 += p[3 * S_];
        a4 += p[4 * S_];
        a5 += p[5 * S_];
        a6 += p[6 * S_];
        a7 += p[7 * S_];
        p += 8 * S_;
    }
    float sum = ((a0 + a1) + (a2 + a3)) + ((a4 + a5) + (a6 + a7));

    g_part1[((size_t)b * NPART + (size_t)lh * CH + chunk) * S_ + tid] = sum;
}

// ---------------------------------------------------------------------------
// Kernel 2: collapse 288 partials -> final s[b][col] in one wide pass.
// Block = 256 threads = (32 columns x 8 k-groups); grid = (25 colsegs, 4 b).
// For a fixed (kgroup, k) iteration the 32 lanes read 128 contiguous bytes.
// ---------------------------------------------------------------------------
__global__ __launch_bounds__(256, 8)
void reduce2_kernel() {
    __shared__ float sm[KGRP][32];

    const int tid  = threadIdx.x;
    const int lane = tid & 31;
    const int kg   = tid >> 5;                    // 0..7
    const int col  = blockIdx.x * 32 + lane;      // 0..799 (guard < 784)
    const int b    = blockIdx.y;

    float s = 0.f;
    if (col < NP) {
        // output column col = source column (col + 1)  (skip CLS)
        const float* __restrict__ src =
            g_part1 + ((size_t)b * NPART + (size_t)kg * PER_KG) * S_ + (col + 1);
        #pragma unroll
        for (int k = 0; k < PER_KG; ++k) s += src[(size_t)k * S_];
    }
    sm[kg][lane] = s;
    __syncthreads();

    if (kg == 0 && col < NP) {
        // fixed pairwise tree (deterministic)
        float t0 = sm[0][lane] + sm[1][lane];
        float t1 = sm[2][lane] + sm[3][lane];
        float t2 = sm[4][lane] + sm[5][lane];
        float t3 = sm[6][lane] + sm[7][lane];
        float tot = (t0 + t1) + (t2 + t3);
        g_s[(size_t)b * NP + col] = tot * (1.0f / (L_ * H_));
    }
}

// ---------------------------------------------------------------------------
// Kernel 3: per-batch finalize. LayerNorm, then kthvalue threshold via 4-round
// 8-bit radix select on the monotone uint transform (exact k-th value, ties
// handled identically to sorting). Mask compared in key domain (sigmoid and
// the transform are monotone, so p > thr  <=>  key > key_thr).
// ---------------------------------------------------------------------------
__global__ __launch_bounds__(1024, 1)
void finalize_kernel(const float* __restrict__ gamma,
                     const float* __restrict__ beta,
                     float* __restrict__ out) {
    __shared__ float red[1024];
    __shared__ unsigned skey[NP];
    __shared__ int hist[256];
    __shared__ float s_mu, s_rstd;
    __shared__ unsigned s_prefix;
    __shared__ int s_k;

    const int b = blockIdx.x;
    const int t = threadIdx.x;

    const float s = (t < NP) ? g_s[(size_t)b * NP + t] : 0.f;

    // mean
    red[t] = s;
    __syncthreads();
    for (int o = 512; o > 0; o >>= 1) {
        if (t < o) red[t] += red[t + o];
        __syncthreads();
    }
    if (t == 0) s_mu = red[0] / NP;
    __syncthreads();
    const float mu = s_mu;

    // variance
    const float d = (t < NP) ? (s - mu) : 0.f;
    red[t] = d * d;
    __syncthreads();
    for (int o = 512; o > 0; o >>= 1) {
        if (t < o) red[t] += red[t + o];
        __syncthreads();
    }
    if (t == 0) {
        s_rstd = rsqrtf(red[0] / NP + LN_EPS);
        s_prefix = 0u;
        s_k = KS;
    }
    __syncthreads();

    // LN value -> monotone uint key
    unsigned mykey = 0u;
    if (t < NP) {
        const float v = d * s_rstd * gamma[t] + beta[t];
        unsigned u = __float_as_uint(v);
        u = (u & 0x80000000u) ? ~u : (u | 0x80000000u);
        skey[t] = u;
        mykey = u;
    }
    __syncthreads();

    // 4-round radix select (MSB first) for the KS-th smallest key
    #pragma unroll
    for (int r = 0; r < 4; ++r) {
        const int sh = 24 - 8 * r;

        if (t < 256) hist[t] = 0;
        __syncthreads();

        if (t < NP) {
            bool act = (r == 0) ||
                       ((mykey >> (sh + 8)) == (s_prefix >> (sh + 8)));
            if (act) atomicAdd(&hist[(mykey >> sh) & 0xFFu], 1);
        }
        __syncthreads();

        if (t < 32) {
            // lane t owns bins 8t..8t+7
            int c[8], lsum = 0;
            #pragma unroll
            for (int i = 0; i < 8; ++i) { c[i] = hist[t * 8 + i]; lsum += c[i]; }
            // inclusive warp scan of lane sums
            int incl = lsum;
            #pragma unroll
            for (int o = 1; o < 32; o <<= 1) {
                int n = __shfl_up_sync(0xFFFFFFFFu, incl, o);
                if (t >= o) incl += n;
            }
            const int excl = incl - lsum;
            const int kk = s_k;
            if (excl < kk && kk <= incl) {     // exactly one lane
                int run = excl, bin = 0, newk = 0;
                #pragma unroll
                for (int i = 0; i < 8; ++i) {
                    if (newk == 0 && run + c[i] >= kk) { bin = t * 8 + i; newk = kk - run; }
                    run += c[i];
                }
                s_prefix |= (unsigned)bin << sh;
                s_k = newk;
            }
        }
        __syncthreads();
    }

    if (t < NP)
        out[(size_t)b * NP + t] = (skey[t] > s_prefix) ? 1.0f : 0.0f;
}

// ---------------------------------------------------------------------------
extern "C" void kernel_launch(void* const* d_in, const int* in_sizes, int n_in,
                              void* d_out, int out_size) {
    const float* att   = (const float*)d_in[0];
    const float* gamma = (const float*)d_in[1];
    const float* beta  = (const float*)d_in[2];
    float* out = (float*)d_out;

    colsum_kernel<<<dim3(CH, 144, B_), 800>>>(att);
    reduce2_kernel<<<dim3(25, B_), 256>>>();
    finalize_kernel<<<B_, 1024>>>(gamma, beta, out);
}